// round 3
// baseline (speedup 1.0000x reference)
#include <cuda_runtime.h>
#include <cuda_bf16.h>
#include <math.h>

// ---------------------------------------------------------------------------
// ViT block: x + proj(attn(LN1(x))) -> +MLP(LN2(.))
// B=16, C=384, H=W=32 (N=1024), NH=8, HD=48, HID=1536
// Round 3 design: fused flash attention (no materialized S) + dense rel-pos
// bias precompute + 128x128x8 fp32 SGEMM (8x8 micro) for all dense GEMMs.
// ---------------------------------------------------------------------------

constexpr int Bc   = 16;
constexpr int Cc   = 384;
constexpr int Nc   = 1024;     // H*W
constexpr int NHc  = 8;
constexpr int HDc  = 48;
constexpr int MIDc = 384;      // NH*HD
constexpr int HIDc = 1536;
constexpr int Mtok = Bc * Nc;  // 16384 tokens
constexpr int CN   = Cc * Nc;  // per-image NCHW plane stride

// -------------------------- scratch (static, no allocs) --------------------
__device__ __align__(256) float g_xln [Mtok * Cc];               // LN1 out, token-major
__device__ __align__(256) float g_Q   [Bc * NHc * Nc * HDc];     // [bh, n, d]
__device__ __align__(256) float g_K   [Bc * NHc * Nc * HDc];
__device__ __align__(256) float g_V   [Bc * NHc * Nc * HDc];
__device__ __align__(256) float g_bias[NHc * Nc * Nc];           // 32MB dense bias
__device__ __align__(256) float g_O   [Mtok * MIDc];             // attn out, token-major
__device__ __align__(256) float g_x2t [Mtok * Cc];               // x + proj, token-major
__device__ __align__(256) float g_h2t [Mtok * Cc];               // LN2 out
__device__ __align__(256) float g_m1  [Mtok * HIDc];             // MLP hidden

// ---------------------------------------------------------------------------
// 128x128 tile SGEMM mainloop: C = A[M,K] * W[N,K]^T, BK=8, 256 threads,
// 8x8 micro-tile per thread split as (ty*4 + {0..3}, +64) x (tx*4 + {0..3}, +64).
// KDIM compile-time, multiple of 8.
// ---------------------------------------------------------------------------
template<int KDIM>
__device__ __forceinline__ void gemm128(const float* __restrict__ A,
                                        const float* __restrict__ W,
                                        int m0, int n0, float (&acc)[2][4][2][4])
{
    __shared__ __align__(16) float sA[8][128];
    __shared__ __align__(16) float sW[8][128];
    const int tid = threadIdx.x;
    const int tx  = tid & 15;          // 0..15 -> n micro cols
    const int ty  = tid >> 4;          // 0..15 -> m micro rows
    const int lr  = tid >> 1;          // 0..127 tile row loaded by this thread
    const int lk  = (tid & 1) << 2;    // 0 or 4

#pragma unroll
    for (int a = 0; a < 2; a++)
#pragma unroll
        for (int i = 0; i < 4; i++)
#pragma unroll
            for (int b = 0; b < 2; b++)
#pragma unroll
                for (int j = 0; j < 4; j++) acc[a][i][b][j] = 0.f;

    const float* Ap = A + (size_t)(m0 + lr) * KDIM + lk;
    const float* Wp = W + (size_t)(n0 + lr) * KDIM + lk;

    for (int k0 = 0; k0 < KDIM; k0 += 8) {
        const float4 av = *(const float4*)(Ap + k0);
        const float4 wv = *(const float4*)(Wp + k0);
        __syncthreads();
        sA[lk + 0][lr] = av.x; sA[lk + 1][lr] = av.y;
        sA[lk + 2][lr] = av.z; sA[lk + 3][lr] = av.w;
        sW[lk + 0][lr] = wv.x; sW[lk + 1][lr] = wv.y;
        sW[lk + 2][lr] = wv.z; sW[lk + 3][lr] = wv.w;
        __syncthreads();
#pragma unroll
        for (int kk = 0; kk < 8; kk++) {
            const float4 a0 = *(const float4*)&sA[kk][ty << 2];
            const float4 a1 = *(const float4*)&sA[kk][64 + (ty << 2)];
            const float4 w0 = *(const float4*)&sW[kk][tx << 2];
            const float4 w1 = *(const float4*)&sW[kk][64 + (tx << 2)];
            const float am[2][4] = {{a0.x, a0.y, a0.z, a0.w}, {a1.x, a1.y, a1.z, a1.w}};
            const float wn[2][4] = {{w0.x, w0.y, w0.z, w0.w}, {w1.x, w1.y, w1.z, w1.w}};
#pragma unroll
            for (int a = 0; a < 2; a++)
#pragma unroll
                for (int i = 0; i < 4; i++)
#pragma unroll
                    for (int b = 0; b < 2; b++)
#pragma unroll
                        for (int j = 0; j < 4; j++)
                            acc[a][i][b][j] = fmaf(am[a][i], wn[b][j], acc[a][i][b][j]);
        }
    }
}

// row/col helpers for the 8x8 split micro-tile
__device__ __forceinline__ int micro_row(int m0, int ty, int a, int i) {
    return m0 + (a ? 64 : 0) + (ty << 2) + i;
}
__device__ __forceinline__ int micro_col(int n0, int tx, int b, int j) {
    return n0 + (b ? 64 : 0) + (tx << 2) + j;
}

// -------------------------------- LN1 (channel LN on NCHW) -----------------
__global__ void ln1_kernel(const float* __restrict__ x,
                           const float* __restrict__ g,
                           const float* __restrict__ be)
{
    const int b  = blockIdx.x >> 5;
    const int n0 = (blockIdx.x & 31) << 5;
    const int tx = threadIdx.x, ty = threadIdx.y;
    const float* xb = x + (size_t)b * CN + n0 + tx;

    float s = 0.f, s2 = 0.f;
    for (int c = ty; c < Cc; c += 8) {
        float v = xb[c * Nc];
        s += v; s2 += v * v;
    }
    __shared__ float ss[8][33], sq[8][33];
    ss[ty][tx] = s; sq[ty][tx] = s2;
    __syncthreads();
    s = 0.f; s2 = 0.f;
#pragma unroll
    for (int j = 0; j < 8; j++) { s += ss[j][tx]; s2 += sq[j][tx]; }
    const float mean = s * (1.f / Cc);
    const float rstd = rsqrtf(s2 * (1.f / Cc) - mean * mean + 1e-5f);

    float* orow = g_xln + ((size_t)(b << 10) + n0 + tx) * Cc;
    for (int c = ty; c < Cc; c += 8) {
        float v = xb[c * Nc];
        orow[c] = (v - mean) * rstd * g[c] + be[c];
    }
}

// -------------------------------- dense bias precompute --------------------
__global__ void bias_pre_kernel(const int* __restrict__ rel_index,
                                const float* __restrict__ rpb)
{
    const int n = blockIdx.x;
    const int h = blockIdx.y;
    const int m = threadIdx.x << 2;
    const int4 ri = *(const int4*)(rel_index + n * Nc + m);
    float4 r;
    r.x = rpb[ri.x * NHc + h];
    r.y = rpb[ri.y * NHc + h];
    r.z = rpb[ri.z * NHc + h];
    r.w = rpb[ri.w * NHc + h];
    *(float4*)(g_bias + (((size_t)h << 10) + n) * Nc + m) = r;
}

// -------------------------------- QKV projection ---------------------------
// Y[M,1152] = xln @ [wq;wkv]^T + bias, scattered into Q/K/V [bh,n,d].
__global__ __launch_bounds__(256) void qkv_gemm(
        const float* __restrict__ wq, const float* __restrict__ bq,
        const float* __restrict__ wkv, const float* __restrict__ bkv)
{
    const int n0 = blockIdx.x * 128;
    const int m0 = blockIdx.y * 128;
    const float* Wp = (n0 < MIDc) ? wq : (wkv - (size_t)MIDc * Cc);
    const float* bp = (n0 < MIDc) ? bq : (bkv - MIDc);

    float acc[2][4][2][4];
    gemm128<Cc>(g_xln, Wp, m0, n0, acc);

    const int tx = threadIdx.x & 15, ty = threadIdx.x >> 4;
#pragma unroll
    for (int a = 0; a < 2; a++)
#pragma unroll
    for (int i = 0; i < 4; i++) {
        const int m = micro_row(m0, ty, a, i);
        const int b = m >> 10, n = m & 1023;
#pragma unroll
        for (int bb = 0; bb < 2; bb++)
#pragma unroll
        for (int j = 0; j < 4; j++) {
            const int o = micro_col(n0, tx, bb, j);
            const float val = acc[a][i][bb][j] + bp[o];
            const int oo = (o >= 2 * MIDc) ? o - 2 * MIDc : (o >= MIDc ? o - MIDc : o);
            const int hh = oo / HDc, d = oo - hh * HDc;
            const size_t idx = ((size_t)(b * NHc + hh) * Nc + n) * HDc + d;
            if (o < MIDc)          g_Q[idx] = val;
            else if (o < 2 * MIDc) g_K[idx] = val;
            else                   g_V[idx] = val;
        }
    }
}

// -------------------------------- fused flash attention --------------------
// grid (16 q-tiles, 128 bh), 256 threads.
__global__ __launch_bounds__(256) void attn_kernel()
{
    const int q0 = blockIdx.x << 6;
    const int bh = blockIdx.y;
    const int h  = bh & 7;
    const float* Q  = g_Q + (size_t)bh * Nc * HDc;
    const float* K  = g_K + (size_t)bh * Nc * HDc;
    const float* V  = g_V + (size_t)bh * Nc * HDc;
    const float* Bp = g_bias + ((size_t)h << 20);

    __shared__ __align__(16) float sQ[48][68];   // [d][row]
    __shared__ __align__(16) float sK[48][68];   // [d][col]
    __shared__ __align__(16) float sV[64][52];   // [k][d]
    __shared__ __align__(16) float sP[64][68];   // [row][k]

    const int tid = threadIdx.x;
    const int tx  = tid & 15, ty = tid >> 4;
    const int lr  = tid >> 2;            // 0..63 tile row handled by loader
    const int ld0 = (tid & 3) * 12;      // 0,12,24,36

    // ---- load Q tile, transposed into sQ[d][row] ----
    {
        const float4* qr = (const float4*)(Q + (size_t)(q0 + lr) * HDc + ld0);
        float4 a = qr[0], b4 = qr[1], c4 = qr[2];
        float v[12] = {a.x,a.y,a.z,a.w, b4.x,b4.y,b4.z,b4.w, c4.x,c4.y,c4.z,c4.w};
#pragma unroll
        for (int j = 0; j < 12; j++) sQ[ld0 + j][lr] = v[j];
    }

    float m_i[4], l_i[4], accO[4][3];
#pragma unroll
    for (int i = 0; i < 4; i++) {
        m_i[i] = -1e30f; l_i[i] = 0.f;
        accO[i][0] = accO[i][1] = accO[i][2] = 0.f;
    }
    const float scale = 0.14433756729740644f;   // 48^-0.5

    for (int k0 = 0; k0 < Nc; k0 += 64) {
        // ---- load K (transposed) and V tiles ----
        {
            const float4* kr = (const float4*)(K + (size_t)(k0 + lr) * HDc + ld0);
            const float4* vr = (const float4*)(V + (size_t)(k0 + lr) * HDc + ld0);
            float4 ka = kr[0], kb = kr[1], kc = kr[2];
            float4 va = vr[0], vb = vr[1], vc = vr[2];
            __syncthreads();   // previous iteration fully done with smem
            float kv[12] = {ka.x,ka.y,ka.z,ka.w, kb.x,kb.y,kb.z,kb.w, kc.x,kc.y,kc.z,kc.w};
#pragma unroll
            for (int j = 0; j < 12; j++) sK[ld0 + j][lr] = kv[j];
            *(float4*)&sV[lr][ld0 + 0] = va;
            *(float4*)&sV[lr][ld0 + 4] = vb;
            *(float4*)&sV[lr][ld0 + 8] = vc;
        }
        __syncthreads();       // tiles visible

        // ---- S = Q K^T (4x4 per thread) ----
        float s[4][4];
#pragma unroll
        for (int i = 0; i < 4; i++)
#pragma unroll
            for (int j = 0; j < 4; j++) s[i][j] = 0.f;
#pragma unroll
        for (int kk = 0; kk < 48; kk++) {
            float4 a4 = *(const float4*)&sQ[kk][ty << 2];
            float4 b4 = *(const float4*)&sK[kk][tx << 2];
            float a[4] = {a4.x, a4.y, a4.z, a4.w};
            float w[4] = {b4.x, b4.y, b4.z, b4.w};
#pragma unroll
            for (int i = 0; i < 4; i++)
#pragma unroll
                for (int j = 0; j < 4; j++)
                    s[i][j] = fmaf(a[i], w[j], s[i][j]);
        }

        // ---- scale + bias, online softmax update ----
#pragma unroll
        for (int i = 0; i < 4; i++) {
            const int n = q0 + (ty << 2) + i;
            const float4 bi = *(const float4*)(Bp + ((size_t)n << 10) + k0 + (tx << 2));
            s[i][0] = fmaf(s[i][0], scale, bi.x);
            s[i][1] = fmaf(s[i][1], scale, bi.y);
            s[i][2] = fmaf(s[i][2], scale, bi.z);
            s[i][3] = fmaf(s[i][3], scale, bi.w);

            float mx = fmaxf(fmaxf(s[i][0], s[i][1]), fmaxf(s[i][2], s[i][3]));
#pragma unroll
            for (int o = 8; o > 0; o >>= 1) mx = fmaxf(mx, __shfl_xor_sync(~0u, mx, o));

            const float mn = fmaxf(m_i[i], mx);
            const float f  = __expf(m_i[i] - mn);
            m_i[i] = mn;
            s[i][0] = __expf(s[i][0] - mn);
            s[i][1] = __expf(s[i][1] - mn);
            s[i][2] = __expf(s[i][2] - mn);
            s[i][3] = __expf(s[i][3] - mn);
            float rs = s[i][0] + s[i][1] + s[i][2] + s[i][3];
#pragma unroll
            for (int o = 8; o > 0; o >>= 1) rs += __shfl_xor_sync(~0u, rs, o);
            l_i[i] = l_i[i] * f + rs;
            accO[i][0] *= f; accO[i][1] *= f; accO[i][2] *= f;
        }

        // ---- store P tile row-major (float4, conflict-free STS.128) ----
#pragma unroll
        for (int i = 0; i < 4; i++)
            *(float4*)&sP[(ty << 2) + i][tx << 2] =
                make_float4(s[i][0], s[i][1], s[i][2], s[i][3]);
        __syncthreads();       // P visible

        // ---- O += P @ V ----
#pragma unroll
        for (int k4 = 0; k4 < 16; k4++) {
            float4 p4[4];
#pragma unroll
            for (int i = 0; i < 4; i++)
                p4[i] = *(const float4*)&sP[(ty << 2) + i][k4 << 2];
#pragma unroll
            for (int kk = 0; kk < 4; kk++) {
                const float v0 = sV[(k4 << 2) + kk][tx * 3 + 0];
                const float v1 = sV[(k4 << 2) + kk][tx * 3 + 1];
                const float v2 = sV[(k4 << 2) + kk][tx * 3 + 2];
#pragma unroll
                for (int i = 0; i < 4; i++) {
                    const float p = (&p4[i].x)[kk];
                    accO[i][0] = fmaf(p, v0, accO[i][0]);
                    accO[i][1] = fmaf(p, v1, accO[i][1]);
                    accO[i][2] = fmaf(p, v2, accO[i][2]);
                }
            }
        }
    }

    // ---- normalize and write O (token-major [b*1024+n][384]) ----
    const int b = bh >> 3;
#pragma unroll
    for (int i = 0; i < 4; i++) {
        const int n = q0 + (ty << 2) + i;
        const float inv = 1.f / l_i[i];
        float* orow = g_O + ((size_t)(b << 10) + n) * MIDc + h * HDc + tx * 3;
        orow[0] = accO[i][0] * inv;
        orow[1] = accO[i][1] * inv;
        orow[2] = accO[i][2] * inv;
    }
}

// -------------------------------- proj + residual --------------------------
__global__ __launch_bounds__(256) void proj_gemm(
        const float* __restrict__ wproj, const float* __restrict__ bproj,
        const float* __restrict__ x)
{
    const int n0 = blockIdx.x * 128;
    const int m0 = blockIdx.y * 128;
    float acc[2][4][2][4];
    gemm128<MIDc>(g_O, wproj, m0, n0, acc);

    const int tx = threadIdx.x & 15, ty = threadIdx.x >> 4;
#pragma unroll
    for (int a = 0; a < 2; a++)
#pragma unroll
    for (int i = 0; i < 4; i++) {
        const int m = micro_row(m0, ty, a, i);
        const int b = m >> 10, n = m & 1023;
#pragma unroll
        for (int bb = 0; bb < 2; bb++)
#pragma unroll
        for (int j = 0; j < 4; j++) {
            const int o = micro_col(n0, tx, bb, j);
            const float val = acc[a][i][bb][j] + bproj[o]
                            + x[(size_t)b * CN + (size_t)o * Nc + n];
            g_x2t[(size_t)m * Cc + o] = val;
        }
    }
}

// -------------------------------- LN2 (token-major rows) -------------------
__global__ void ln2_kernel(const float* __restrict__ g, const float* __restrict__ be)
{
    const int t    = blockIdx.x * 8 + (threadIdx.x >> 5);
    const int lane = threadIdx.x & 31;
    const float4* xr = (const float4*)(g_x2t + (size_t)t * Cc);

    float4 v[3];
    float s = 0.f, s2 = 0.f;
#pragma unroll
    for (int i = 0; i < 3; i++) {
        v[i] = xr[lane + 32 * i];
        s  += v[i].x + v[i].y + v[i].z + v[i].w;
        s2 += v[i].x * v[i].x + v[i].y * v[i].y + v[i].z * v[i].z + v[i].w * v[i].w;
    }
#pragma unroll
    for (int o = 16; o > 0; o >>= 1) {
        s  += __shfl_xor_sync(~0u, s, o);
        s2 += __shfl_xor_sync(~0u, s2, o);
    }
    const float mean = s * (1.f / Cc);
    const float rstd = rsqrtf(s2 * (1.f / Cc) - mean * mean + 1e-5f);

    const float4* g4 = (const float4*)g;
    const float4* b4 = (const float4*)be;
    float4* orow = (float4*)(g_h2t + (size_t)t * Cc);
#pragma unroll
    for (int i = 0; i < 3; i++) {
        const int c4 = lane + 32 * i;
        const float4 gg = g4[c4], bb = b4[c4], vv = v[i];
        float4 r;
        r.x = (vv.x - mean) * rstd * gg.x + bb.x;
        r.y = (vv.y - mean) * rstd * gg.y + bb.y;
        r.z = (vv.z - mean) * rstd * gg.z + bb.z;
        r.w = (vv.w - mean) * rstd * gg.w + bb.w;
        orow[c4] = r;
    }
}

// -------------------------------- MLP fc1 + exact GELU ---------------------
__global__ __launch_bounds__(256) void mlp1_gemm(
        const float* __restrict__ w1, const float* __restrict__ b1)
{
    const int n0 = blockIdx.x * 128;
    const int m0 = blockIdx.y * 128;
    float acc[2][4][2][4];
    gemm128<Cc>(g_h2t, w1, m0, n0, acc);

    const int tx = threadIdx.x & 15, ty = threadIdx.x >> 4;
#pragma unroll
    for (int a = 0; a < 2; a++)
#pragma unroll
    for (int i = 0; i < 4; i++) {
        const int m = micro_row(m0, ty, a, i);
#pragma unroll
        for (int bb = 0; bb < 2; bb++)
#pragma unroll
        for (int j = 0; j < 4; j++) {
            const int o = micro_col(n0, tx, bb, j);
            const float val = acc[a][i][bb][j] + b1[o];
            const float gl  = 0.5f * val * (1.f + erff(val * 0.70710678118654752f));
            g_m1[(size_t)m * HIDc + o] = gl;
        }
    }
}

// -------------------------------- MLP fc2 + final residual, NCHW out -------
__global__ __launch_bounds__(256) void mlp2_gemm(
        const float* __restrict__ w2, const float* __restrict__ b2,
        float* __restrict__ out)
{
    const int n0 = blockIdx.x * 128;
    const int m0 = blockIdx.y * 128;
    float acc[2][4][2][4];
    gemm128<HIDc>(g_m1, w2, m0, n0, acc);

    const int tx = threadIdx.x & 15, ty = threadIdx.x >> 4;
#pragma unroll
    for (int a = 0; a < 2; a++)
#pragma unroll
    for (int i = 0; i < 4; i++) {
        const int m = micro_row(m0, ty, a, i);
        const int b = m >> 10, n = m & 1023;
#pragma unroll
        for (int bb = 0; bb < 2; bb++)
#pragma unroll
        for (int j = 0; j < 4; j++) {
            const int o = micro_col(n0, tx, bb, j);
            const float val = acc[a][i][bb][j] + b2[o] + g_x2t[(size_t)m * Cc + o];
            out[(size_t)b * CN + (size_t)o * Nc + n] = val;
        }
    }
}

// ---------------------------------------------------------------------------
extern "C" void kernel_launch(void* const* d_in, const int* in_sizes, int n_in,
                              void* d_out, int out_size)
{
    const float* x     = (const float*)d_in[0];
    const float* rpb   = (const float*)d_in[1];
    const int*   ridx  = (const int*)  d_in[2];
    const float* ln1g  = (const float*)d_in[3];
    const float* ln1b  = (const float*)d_in[4];
    const float* ln2g  = (const float*)d_in[5];
    const float* ln2b  = (const float*)d_in[6];
    const float* wq    = (const float*)d_in[7];
    const float* bq    = (const float*)d_in[8];
    const float* wkv   = (const float*)d_in[9];
    const float* bkv   = (const float*)d_in[10];
    const float* wproj = (const float*)d_in[11];
    const float* bproj = (const float*)d_in[12];
    const float* w1    = (const float*)d_in[13];
    const float* b1    = (const float*)d_in[14];
    const float* w2    = (const float*)d_in[15];
    const float* b2    = (const float*)d_in[16];
    float* out = (float*)d_out;

    ln1_kernel     <<<Bc * (Nc / 32), dim3(32, 8)>>>(x, ln1g, ln1b);
    bias_pre_kernel<<<dim3(Nc, NHc), 256>>>(ridx, rpb);
    qkv_gemm       <<<dim3(9,  Mtok / 128), 256>>>(wq, bq, wkv, bkv);
    attn_kernel    <<<dim3(16, Bc * NHc), 256>>>();
    proj_gemm      <<<dim3(3,  Mtok / 128), 256>>>(wproj, bproj, x);
    ln2_kernel     <<<Mtok / 8, 256>>>(ln2g, ln2b);
    mlp1_gemm      <<<dim3(12, Mtok / 128), 256>>>(w1, b1);
    mlp2_gemm      <<<dim3(3,  Mtok / 128), 256>>>(w2, b2, out);
}

// round 12
// speedup vs baseline: 1.1013x; 1.1013x over previous
#include <cuda_runtime.h>
#include <cuda_bf16.h>
#include <math.h>

// ---------------------------------------------------------------------------
// ViT block: x + proj(attn(LN1(x))) -> +MLP(LN2(.))
// B=16, C=384, H=W=32 (N=1024), NH=8, HD=48, HID=1536
// Round 12 (resubmit of unmeasured round 4 design): attn -> no-max softmax
// (bounded logits), V^T smem for vectorized PV, bias prefetch; dense GEMMs ->
// double-buffered 128x128x8 SGEMM.
// ---------------------------------------------------------------------------

constexpr int Bc   = 16;
constexpr int Cc   = 384;
constexpr int Nc   = 1024;     // H*W
constexpr int NHc  = 8;
constexpr int HDc  = 48;
constexpr int MIDc = 384;      // NH*HD
constexpr int HIDc = 1536;
constexpr int Mtok = Bc * Nc;  // 16384 tokens
constexpr int CN   = Cc * Nc;  // per-image NCHW plane stride

// -------------------------- scratch (static, no allocs) --------------------
__device__ __align__(256) float g_xln [Mtok * Cc];               // LN1 out, token-major
__device__ __align__(256) float g_Q   [Bc * NHc * Nc * HDc];     // [bh, n, d]
__device__ __align__(256) float g_K   [Bc * NHc * Nc * HDc];
__device__ __align__(256) float g_V   [Bc * NHc * Nc * HDc];
__device__ __align__(256) float g_bias[NHc * Nc * Nc];           // 32MB dense bias
__device__ __align__(256) float g_O   [Mtok * MIDc];             // attn out, token-major
__device__ __align__(256) float g_x2t [Mtok * Cc];               // x + proj, token-major
__device__ __align__(256) float g_h2t [Mtok * Cc];               // LN2 out
__device__ __align__(256) float g_m1  [Mtok * HIDc];             // MLP hidden

// ---------------------------------------------------------------------------
// 128x128 tile SGEMM mainloop: C = A[M,K] * W[N,K]^T, BK=8, 256 threads,
// 8x8 micro split as (ty*4+{0..3}, +64) x (tx*4+{0..3}, +64).
// Double-buffered smem: one barrier per k-step, loads overlap compute.
// ---------------------------------------------------------------------------
template<int KDIM>
__device__ __forceinline__ void gemm128(const float* __restrict__ A,
                                        const float* __restrict__ W,
                                        int m0, int n0, float (&acc)[2][4][2][4])
{
    __shared__ __align__(16) float sA[2][8][128];
    __shared__ __align__(16) float sW[2][8][128];
    const int tid = threadIdx.x;
    const int tx  = tid & 15;
    const int ty  = tid >> 4;
    const int lr  = tid >> 1;          // 0..127 tile row loaded by this thread
    const int lk  = (tid & 1) << 2;    // 0 or 4

#pragma unroll
    for (int a = 0; a < 2; a++)
#pragma unroll
        for (int i = 0; i < 4; i++)
#pragma unroll
            for (int b = 0; b < 2; b++)
#pragma unroll
                for (int j = 0; j < 4; j++) acc[a][i][b][j] = 0.f;

    const float* Ap = A + (size_t)(m0 + lr) * KDIM + lk;
    const float* Wp = W + (size_t)(n0 + lr) * KDIM + lk;

    // prologue: fill buffer 0
    float4 av = *(const float4*)Ap;
    float4 wv = *(const float4*)Wp;
    sA[0][lk + 0][lr] = av.x; sA[0][lk + 1][lr] = av.y;
    sA[0][lk + 2][lr] = av.z; sA[0][lk + 3][lr] = av.w;
    sW[0][lk + 0][lr] = wv.x; sW[0][lk + 1][lr] = wv.y;
    sW[0][lk + 2][lr] = wv.z; sW[0][lk + 3][lr] = wv.w;
    __syncthreads();

    constexpr int NK = KDIM / 8;
#pragma unroll 2
    for (int it = 0; it < NK; ++it) {
        const int cur = it & 1;
        if (it + 1 < NK) {                       // issue next tile's loads early
            av = *(const float4*)(Ap + (it + 1) * 8);
            wv = *(const float4*)(Wp + (it + 1) * 8);
        }
#pragma unroll
        for (int kk = 0; kk < 8; kk++) {
            const float4 a0 = *(const float4*)&sA[cur][kk][ty << 2];
            const float4 a1 = *(const float4*)&sA[cur][kk][64 + (ty << 2)];
            const float4 w0 = *(const float4*)&sW[cur][kk][tx << 2];
            const float4 w1 = *(const float4*)&sW[cur][kk][64 + (tx << 2)];
            const float am[2][4] = {{a0.x, a0.y, a0.z, a0.w}, {a1.x, a1.y, a1.z, a1.w}};
            const float wn[2][4] = {{w0.x, w0.y, w0.z, w0.w}, {w1.x, w1.y, w1.z, w1.w}};
#pragma unroll
            for (int a = 0; a < 2; a++)
#pragma unroll
                for (int i = 0; i < 4; i++)
#pragma unroll
                    for (int b = 0; b < 2; b++)
#pragma unroll
                        for (int j = 0; j < 4; j++)
                            acc[a][i][b][j] = fmaf(am[a][i], wn[b][j], acc[a][i][b][j]);
        }
        if (it + 1 < NK) {
            const int nxt = cur ^ 1;
            sA[nxt][lk + 0][lr] = av.x; sA[nxt][lk + 1][lr] = av.y;
            sA[nxt][lk + 2][lr] = av.z; sA[nxt][lk + 3][lr] = av.w;
            sW[nxt][lk + 0][lr] = wv.x; sW[nxt][lk + 1][lr] = wv.y;
            sW[nxt][lk + 2][lr] = wv.z; sW[nxt][lk + 3][lr] = wv.w;
            __syncthreads();
        }
    }
}

__device__ __forceinline__ int micro_row(int m0, int ty, int a, int i) {
    return m0 + (a ? 64 : 0) + (ty << 2) + i;
}
__device__ __forceinline__ int micro_col(int n0, int tx, int b, int j) {
    return n0 + (b ? 64 : 0) + (tx << 2) + j;
}

// -------------------------------- LN1 (channel LN on NCHW) -----------------
__global__ void ln1_kernel(const float* __restrict__ x,
                           const float* __restrict__ g,
                           const float* __restrict__ be)
{
    const int b  = blockIdx.x >> 5;
    const int n0 = (blockIdx.x & 31) << 5;
    const int tx = threadIdx.x, ty = threadIdx.y;
    const float* xb = x + (size_t)b * CN + n0 + tx;

    float s = 0.f, s2 = 0.f;
    for (int c = ty; c < Cc; c += 8) {
        float v = xb[c * Nc];
        s += v; s2 += v * v;
    }
    __shared__ float ss[8][33], sq[8][33];
    ss[ty][tx] = s; sq[ty][tx] = s2;
    __syncthreads();
    s = 0.f; s2 = 0.f;
#pragma unroll
    for (int j = 0; j < 8; j++) { s += ss[j][tx]; s2 += sq[j][tx]; }
    const float mean = s * (1.f / Cc);
    const float rstd = rsqrtf(s2 * (1.f / Cc) - mean * mean + 1e-5f);

    float* orow = g_xln + ((size_t)(b << 10) + n0 + tx) * Cc;
    for (int c = ty; c < Cc; c += 8) {
        float v = xb[c * Nc];
        orow[c] = (v - mean) * rstd * g[c] + be[c];
    }
}

// -------------------------------- dense bias precompute --------------------
__global__ void bias_pre_kernel(const int* __restrict__ rel_index,
                                const float* __restrict__ rpb)
{
    const int n = blockIdx.x;
    const int h = blockIdx.y;
    const int m = threadIdx.x << 2;
    const int4 ri = *(const int4*)(rel_index + n * Nc + m);
    float4 r;
    r.x = rpb[ri.x * NHc + h];
    r.y = rpb[ri.y * NHc + h];
    r.z = rpb[ri.z * NHc + h];
    r.w = rpb[ri.w * NHc + h];
    *(float4*)(g_bias + (((size_t)h << 10) + n) * Nc + m) = r;
}

// -------------------------------- QKV projection ---------------------------
__global__ __launch_bounds__(256) void qkv_gemm(
        const float* __restrict__ wq, const float* __restrict__ bq,
        const float* __restrict__ wkv, const float* __restrict__ bkv)
{
    const int n0 = blockIdx.x * 128;
    const int m0 = blockIdx.y * 128;
    const float* Wp = (n0 < MIDc) ? wq : (wkv - (size_t)MIDc * Cc);
    const float* bp = (n0 < MIDc) ? bq : (bkv - MIDc);

    float acc[2][4][2][4];
    gemm128<Cc>(g_xln, Wp, m0, n0, acc);

    const int tx = threadIdx.x & 15, ty = threadIdx.x >> 4;
#pragma unroll
    for (int a = 0; a < 2; a++)
#pragma unroll
    for (int i = 0; i < 4; i++) {
        const int m = micro_row(m0, ty, a, i);
        const int b = m >> 10, n = m & 1023;
#pragma unroll
        for (int bb = 0; bb < 2; bb++)
#pragma unroll
        for (int j = 0; j < 4; j++) {
            const int o = micro_col(n0, tx, bb, j);
            const float val = acc[a][i][bb][j] + bp[o];
            const int oo = (o >= 2 * MIDc) ? o - 2 * MIDc : (o >= MIDc ? o - MIDc : o);
            const int hh = oo / HDc, d = oo - hh * HDc;
            const size_t idx = ((size_t)(b * NHc + hh) * Nc + n) * HDc + d;
            if (o < MIDc)          g_Q[idx] = val;
            else if (o < 2 * MIDc) g_K[idx] = val;
            else                   g_V[idx] = val;
        }
    }
}

// -------------------------------- fused flash attention --------------------
// grid (16 q-tiles, 128 bh), 256 threads. No-max softmax (logits bounded),
// per-thread row-sum partials reduced once at the end. V kept transposed.
__global__ __launch_bounds__(256) void attn_kernel()
{
    const int q0 = blockIdx.x << 6;
    const int bh = blockIdx.y;
    const int h  = bh & 7;
    const float* Q  = g_Q + (size_t)bh * Nc * HDc;
    const float* K  = g_K + (size_t)bh * Nc * HDc;
    const float* V  = g_V + (size_t)bh * Nc * HDc;
    const float* Bp = g_bias + ((size_t)h << 20);

    __shared__ __align__(16) float sQ [48][68];   // [d][row]
    __shared__ __align__(16) float sK [48][68];   // [d][col]
    __shared__ __align__(16) float sVT[48][68];   // [d][k]  (V transposed)
    __shared__ __align__(16) float sP [64][68];   // [row][k]

    const int tid = threadIdx.x;
    const int tx  = tid & 15, ty = tid >> 4;
    const int lr  = tid >> 2;            // 0..63 tile row handled by loader
    const int ld0 = (tid & 3) * 12;      // 0,12,24,36

    // ---- load Q tile, transposed into sQ[d][row] ----
    {
        const float4* qr = (const float4*)(Q + (size_t)(q0 + lr) * HDc + ld0);
        float4 a = qr[0], b4 = qr[1], c4 = qr[2];
        float v[12] = {a.x,a.y,a.z,a.w, b4.x,b4.y,b4.z,b4.w, c4.x,c4.y,c4.z,c4.w};
#pragma unroll
        for (int j = 0; j < 12; j++) sQ[ld0 + j][lr] = v[j];
    }

    float lsum[4] = {0.f, 0.f, 0.f, 0.f};
    float accO[4][3];
#pragma unroll
    for (int i = 0; i < 4; i++) accO[i][0] = accO[i][1] = accO[i][2] = 0.f;
    const float scale = 0.14433756729740644f;   // 48^-0.5

    for (int k0 = 0; k0 < Nc; k0 += 64) {
        // ---- load K and V tiles, both transposed [d][k] ----
        {
            const float4* kr = (const float4*)(K + (size_t)(k0 + lr) * HDc + ld0);
            const float4* vr = (const float4*)(V + (size_t)(k0 + lr) * HDc + ld0);
            float4 ka = kr[0], kb = kr[1], kc = kr[2];
            float4 va = vr[0], vb = vr[1], vc = vr[2];
            __syncthreads();   // previous iteration fully done with smem
            float kv[12] = {ka.x,ka.y,ka.z,ka.w, kb.x,kb.y,kb.z,kb.w, kc.x,kc.y,kc.z,kc.w};
            float vv[12] = {va.x,va.y,va.z,va.w, vb.x,vb.y,vb.z,vb.w, vc.x,vc.y,vc.z,vc.w};
#pragma unroll
            for (int j = 0; j < 12; j++) {
                sK [ld0 + j][lr] = kv[j];
                sVT[ld0 + j][lr] = vv[j];
            }
        }
        __syncthreads();       // tiles visible

        // ---- prefetch bias (L2) so latency hides under the S GEMM ----
        float4 bi[4];
#pragma unroll
        for (int i = 0; i < 4; i++) {
            const int n = q0 + (ty << 2) + i;
            bi[i] = *(const float4*)(Bp + ((size_t)n << 10) + k0 + (tx << 2));
        }

        // ---- S = Q K^T (4x4 per thread) ----
        float s[4][4];
#pragma unroll
        for (int i = 0; i < 4; i++)
#pragma unroll
            for (int j = 0; j < 4; j++) s[i][j] = 0.f;
#pragma unroll
        for (int kk = 0; kk < 48; kk++) {
            float4 a4 = *(const float4*)&sQ[kk][ty << 2];
            float4 b4 = *(const float4*)&sK[kk][tx << 2];
            float a[4] = {a4.x, a4.y, a4.z, a4.w};
            float w[4] = {b4.x, b4.y, b4.z, b4.w};
#pragma unroll
            for (int i = 0; i < 4; i++)
#pragma unroll
                for (int j = 0; j < 4; j++)
                    s[i][j] = fmaf(a[i], w[j], s[i][j]);
        }

        // ---- exp(scale*s + bias), accumulate per-thread row-sum partials ----
#pragma unroll
        for (int i = 0; i < 4; i++) {
            s[i][0] = __expf(fmaf(s[i][0], scale, bi[i].x));
            s[i][1] = __expf(fmaf(s[i][1], scale, bi[i].y));
            s[i][2] = __expf(fmaf(s[i][2], scale, bi[i].z));
            s[i][3] = __expf(fmaf(s[i][3], scale, bi[i].w));
            lsum[i] += (s[i][0] + s[i][1]) + (s[i][2] + s[i][3]);
        }

        // ---- store P tile row-major (contiguous STS.128) ----
#pragma unroll
        for (int i = 0; i < 4; i++)
            *(float4*)&sP[(ty << 2) + i][tx << 2] =
                make_float4(s[i][0], s[i][1], s[i][2], s[i][3]);
        __syncthreads();       // P visible

        // ---- O += P @ V  (both operands via LDS.128) ----
#pragma unroll
        for (int k4 = 0; k4 < 16; k4++) {
            float4 p4[4];
#pragma unroll
            for (int i = 0; i < 4; i++)
                p4[i] = *(const float4*)&sP[(ty << 2) + i][k4 << 2];
            float4 vt[3];
#pragma unroll
            for (int j = 0; j < 3; j++)
                vt[j] = *(const float4*)&sVT[tx * 3 + j][k4 << 2];
#pragma unroll
            for (int i = 0; i < 4; i++) {
#pragma unroll
                for (int j = 0; j < 3; j++) {
                    accO[i][j] = fmaf(p4[i].x, vt[j].x, accO[i][j]);
                    accO[i][j] = fmaf(p4[i].y, vt[j].y, accO[i][j]);
                    accO[i][j] = fmaf(p4[i].z, vt[j].z, accO[i][j]);
                    accO[i][j] = fmaf(p4[i].w, vt[j].w, accO[i][j]);
                }
            }
        }
    }

    // ---- single row-sum reduction across the 16 tx lanes, then write O ----
    const int b = bh >> 3;
#pragma unroll
    for (int i = 0; i < 4; i++) {
        float l = lsum[i];
#pragma unroll
        for (int o = 8; o > 0; o >>= 1) l += __shfl_xor_sync(~0u, l, o);
        const float inv = 1.f / l;
        const int n = q0 + (ty << 2) + i;
        float* orow = g_O + ((size_t)(b << 10) + n) * MIDc + h * HDc + tx * 3;
        orow[0] = accO[i][0] * inv;
        orow[1] = accO[i][1] * inv;
        orow[2] = accO[i][2] * inv;
    }
}

// -------------------------------- proj + residual --------------------------
__global__ __launch_bounds__(256) void proj_gemm(
        const float* __restrict__ wproj, const float* __restrict__ bproj,
        const float* __restrict__ x)
{
    const int n0 = blockIdx.x * 128;
    const int m0 = blockIdx.y * 128;
    float acc[2][4][2][4];
    gemm128<MIDc>(g_O, wproj, m0, n0, acc);

    const int tx = threadIdx.x & 15, ty = threadIdx.x >> 4;
#pragma unroll
    for (int a = 0; a < 2; a++)
#pragma unroll
    for (int i = 0; i < 4; i++) {
        const int m = micro_row(m0, ty, a, i);
        const int b = m >> 10, n = m & 1023;
#pragma unroll
        for (int bb = 0; bb < 2; bb++)
#pragma unroll
        for (int j = 0; j < 4; j++) {
            const int o = micro_col(n0, tx, bb, j);
            const float val = acc[a][i][bb][j] + bproj[o]
                            + x[(size_t)b * CN + (size_t)o * Nc + n];
            g_x2t[(size_t)m * Cc + o] = val;
        }
    }
}

// -------------------------------- LN2 (token-major rows) -------------------
__global__ void ln2_kernel(const float* __restrict__ g, const float* __restrict__ be)
{
    const int t    = blockIdx.x * 8 + (threadIdx.x >> 5);
    const int lane = threadIdx.x & 31;
    const float4* xr = (const float4*)(g_x2t + (size_t)t * Cc);

    float4 v[3];
    float s = 0.f, s2 = 0.f;
#pragma unroll
    for (int i = 0; i < 3; i++) {
        v[i] = xr[lane + 32 * i];
        s  += v[i].x + v[i].y + v[i].z + v[i].w;
        s2 += v[i].x * v[i].x + v[i].y * v[i].y + v[i].z * v[i].z + v[i].w * v[i].w;
    }
#pragma unroll
    for (int o = 16; o > 0; o >>= 1) {
        s  += __shfl_xor_sync(~0u, s, o);
        s2 += __shfl_xor_sync(~0u, s2, o);
    }
    const float mean = s * (1.f / Cc);
    const float rstd = rsqrtf(s2 * (1.f / Cc) - mean * mean + 1e-5f);

    const float4* g4 = (const float4*)g;
    const float4* b4 = (const float4*)be;
    float4* orow = (float4*)(g_h2t + (size_t)t * Cc);
#pragma unroll
    for (int i = 0; i < 3; i++) {
        const int c4 = lane + 32 * i;
        const float4 gg = g4[c4], bb = b4[c4], vv = v[i];
        float4 r;
        r.x = (vv.x - mean) * rstd * gg.x + bb.x;
        r.y = (vv.y - mean) * rstd * gg.y + bb.y;
        r.z = (vv.z - mean) * rstd * gg.z + bb.z;
        r.w = (vv.w - mean) * rstd * gg.w + bb.w;
        orow[c4] = r;
    }
}

// -------------------------------- MLP fc1 + exact GELU ---------------------
__global__ __launch_bounds__(256) void mlp1_gemm(
        const float* __restrict__ w1, const float* __restrict__ b1)
{
    const int n0 = blockIdx.x * 128;
    const int m0 = blockIdx.y * 128;
    float acc[2][4][2][4];
    gemm128<Cc>(g_h2t, w1, m0, n0, acc);

    const int tx = threadIdx.x & 15, ty = threadIdx.x >> 4;
#pragma unroll
    for (int a = 0; a < 2; a++)
#pragma unroll
    for (int i = 0; i < 4; i++) {
        const int m = micro_row(m0, ty, a, i);
#pragma unroll
        for (int bb = 0; bb < 2; bb++)
#pragma unroll
        for (int j = 0; j < 4; j++) {
            const int o = micro_col(n0, tx, bb, j);
            const float val = acc[a][i][bb][j] + b1[o];
            const float gl  = 0.5f * val * (1.f + erff(val * 0.70710678118654752f));
            g_m1[(size_t)m * HIDc + o] = gl;
        }
    }
}

// -------------------------------- MLP fc2 + final residual, NCHW out -------
__global__ __launch_bounds__(256) void mlp2_gemm(
        const float* __restrict__ w2, const float* __restrict__ b2,
        float* __restrict__ out)
{
    const int n0 = blockIdx.x * 128;
    const int m0 = blockIdx.y * 128;
    float acc[2][4][2][4];
    gemm128<HIDc>(g_m1, w2, m0, n0, acc);

    const int tx = threadIdx.x & 15, ty = threadIdx.x >> 4;
#pragma unroll
    for (int a = 0; a < 2; a++)
#pragma unroll
    for (int i = 0; i < 4; i++) {
        const int m = micro_row(m0, ty, a, i);
        const int b = m >> 10, n = m & 1023;
#pragma unroll
        for (int bb = 0; bb < 2; bb++)
#pragma unroll
        for (int j = 0; j < 4; j++) {
            const int o = micro_col(n0, tx, bb, j);
            const float val = acc[a][i][bb][j] + b2[o] + g_x2t[(size_t)m * Cc + o];
            out[(size_t)b * CN + (size_t)o * Nc + n] = val;
        }
    }
}

// ---------------------------------------------------------------------------
extern "C" void kernel_launch(void* const* d_in, const int* in_sizes, int n_in,
                              void* d_out, int out_size)
{
    const float* x     = (const float*)d_in[0];
    const float* rpb   = (const float*)d_in[1];
    const int*   ridx  = (const int*)  d_in[2];
    const float* ln1g  = (const float*)d_in[3];
    const float* ln1b  = (const float*)d_in[4];
    const float* ln2g  = (const float*)d_in[5];
    const float* ln2b  = (const float*)d_in[6];
    const float* wq    = (const float*)d_in[7];
    const float* bq    = (const float*)d_in[8];
    const float* wkv   = (const float*)d_in[9];
    const float* bkv   = (const float*)d_in[10];
    const float* wproj = (const float*)d_in[11];
    const float* bproj = (const float*)d_in[12];
    const float* w1    = (const float*)d_in[13];
    const float* b1    = (const float*)d_in[14];
    const float* w2    = (const float*)d_in[15];
    const float* b2    = (const float*)d_in[16];
    float* out = (float*)d_out;

    ln1_kernel     <<<Bc * (Nc / 32), dim3(32, 8)>>>(x, ln1g, ln1b);
    bias_pre_kernel<<<dim3(Nc, NHc), 256>>>(ridx, rpb);
    qkv_gemm       <<<dim3(9,  Mtok / 128), 256>>>(wq, bq, wkv, bkv);
    attn_kernel    <<<dim3(16, Bc * NHc), 256>>>();
    proj_gemm      <<<dim3(3,  Mtok / 128), 256>>>(wproj, bproj, x);
    ln2_kernel     <<<Mtok / 8, 256>>>(ln2g, ln2b);
    mlp1_gemm      <<<dim3(12, Mtok / 128), 256>>>(w1, b1);
    mlp2_gemm      <<<dim3(3,  Mtok / 128), 256>>>(w2, b2, out);
}

// round 15
// speedup vs baseline: 1.1563x; 1.0499x over previous
#include <cuda_runtime.h>
#include <cuda_bf16.h>
#include <math.h>

// ---------------------------------------------------------------------------
// ViT block: x + proj(attn(LN1(x))) -> +MLP(LN2(.))
// B=16, C=384, H=W=32 (N=1024), NH=8, HD=48, HID=1536
// Round 15 (resubmit of unmeasured round 13/14): attn with Br=128 q-tile +
// split 8-row micro (gemm128 pattern) to double FMA per smem wavefront;
// dense GEMMs unchanged (double-buffered 128x128x8 SGEMM).
// ---------------------------------------------------------------------------

constexpr int Bc   = 16;
constexpr int Cc   = 384;
constexpr int Nc   = 1024;     // H*W
constexpr int NHc  = 8;
constexpr int HDc  = 48;
constexpr int MIDc = 384;      // NH*HD
constexpr int HIDc = 1536;
constexpr int Mtok = Bc * Nc;  // 16384 tokens
constexpr int CN   = Cc * Nc;  // per-image NCHW plane stride

// -------------------------- scratch (static, no allocs) --------------------
__device__ __align__(256) float g_xln [Mtok * Cc];               // LN1 out, token-major
__device__ __align__(256) float g_Q   [Bc * NHc * Nc * HDc];     // [bh, n, d]
__device__ __align__(256) float g_K   [Bc * NHc * Nc * HDc];
__device__ __align__(256) float g_V   [Bc * NHc * Nc * HDc];
__device__ __align__(256) float g_bias[NHc * Nc * Nc];           // 32MB dense bias
__device__ __align__(256) float g_O   [Mtok * MIDc];             // attn out, token-major
__device__ __align__(256) float g_x2t [Mtok * Cc];               // x + proj, token-major
__device__ __align__(256) float g_h2t [Mtok * Cc];               // LN2 out
__device__ __align__(256) float g_m1  [Mtok * HIDc];             // MLP hidden

// ---------------------------------------------------------------------------
// 128x128 tile SGEMM mainloop: C = A[M,K] * W[N,K]^T, BK=8, 256 threads,
// 8x8 micro split as (ty*4+{0..3}, +64) x (tx*4+{0..3}, +64).
// Double-buffered smem: one barrier per k-step, loads overlap compute.
// ---------------------------------------------------------------------------
template<int KDIM>
__device__ __forceinline__ void gemm128(const float* __restrict__ A,
                                        const float* __restrict__ W,
                                        int m0, int n0, float (&acc)[2][4][2][4])
{
    __shared__ __align__(16) float sA[2][8][128];
    __shared__ __align__(16) float sW[2][8][128];
    const int tid = threadIdx.x;
    const int tx  = tid & 15;
    const int ty  = tid >> 4;
    const int lr  = tid >> 1;          // 0..127 tile row loaded by this thread
    const int lk  = (tid & 1) << 2;    // 0 or 4

#pragma unroll
    for (int a = 0; a < 2; a++)
#pragma unroll
        for (int i = 0; i < 4; i++)
#pragma unroll
            for (int b = 0; b < 2; b++)
#pragma unroll
                for (int j = 0; j < 4; j++) acc[a][i][b][j] = 0.f;

    const float* Ap = A + (size_t)(m0 + lr) * KDIM + lk;
    const float* Wp = W + (size_t)(n0 + lr) * KDIM + lk;

    // prologue: fill buffer 0
    float4 av = *(const float4*)Ap;
    float4 wv = *(const float4*)Wp;
    sA[0][lk + 0][lr] = av.x; sA[0][lk + 1][lr] = av.y;
    sA[0][lk + 2][lr] = av.z; sA[0][lk + 3][lr] = av.w;
    sW[0][lk + 0][lr] = wv.x; sW[0][lk + 1][lr] = wv.y;
    sW[0][lk + 2][lr] = wv.z; sW[0][lk + 3][lr] = wv.w;
    __syncthreads();

    constexpr int NK = KDIM / 8;
#pragma unroll 2
    for (int it = 0; it < NK; ++it) {
        const int cur = it & 1;
        if (it + 1 < NK) {                       // issue next tile's loads early
            av = *(const float4*)(Ap + (it + 1) * 8);
            wv = *(const float4*)(Wp + (it + 1) * 8);
        }
#pragma unroll
        for (int kk = 0; kk < 8; kk++) {
            const float4 a0 = *(const float4*)&sA[cur][kk][ty << 2];
            const float4 a1 = *(const float4*)&sA[cur][kk][64 + (ty << 2)];
            const float4 w0 = *(const float4*)&sW[cur][kk][tx << 2];
            const float4 w1 = *(const float4*)&sW[cur][kk][64 + (tx << 2)];
            const float am[2][4] = {{a0.x, a0.y, a0.z, a0.w}, {a1.x, a1.y, a1.z, a1.w}};
            const float wn[2][4] = {{w0.x, w0.y, w0.z, w0.w}, {w1.x, w1.y, w1.z, w1.w}};
#pragma unroll
            for (int a = 0; a < 2; a++)
#pragma unroll
                for (int i = 0; i < 4; i++)
#pragma unroll
                    for (int b = 0; b < 2; b++)
#pragma unroll
                        for (int j = 0; j < 4; j++)
                            acc[a][i][b][j] = fmaf(am[a][i], wn[b][j], acc[a][i][b][j]);
        }
        if (it + 1 < NK) {
            const int nxt = cur ^ 1;
            sA[nxt][lk + 0][lr] = av.x; sA[nxt][lk + 1][lr] = av.y;
            sA[nxt][lk + 2][lr] = av.z; sA[nxt][lk + 3][lr] = av.w;
            sW[nxt][lk + 0][lr] = wv.x; sW[nxt][lk + 1][lr] = wv.y;
            sW[nxt][lk + 2][lr] = wv.z; sW[nxt][lk + 3][lr] = wv.w;
            __syncthreads();
        }
    }
}

__device__ __forceinline__ int micro_row(int m0, int ty, int a, int i) {
    return m0 + (a ? 64 : 0) + (ty << 2) + i;
}
__device__ __forceinline__ int micro_col(int n0, int tx, int b, int j) {
    return n0 + (b ? 64 : 0) + (tx << 2) + j;
}

// -------------------------------- LN1 (channel LN on NCHW) -----------------
__global__ void ln1_kernel(const float* __restrict__ x,
                           const float* __restrict__ g,
                           const float* __restrict__ be)
{
    const int b  = blockIdx.x >> 5;
    const int n0 = (blockIdx.x & 31) << 5;
    const int tx = threadIdx.x, ty = threadIdx.y;
    const float* xb = x + (size_t)b * CN + n0 + tx;

    float s = 0.f, s2 = 0.f;
    for (int c = ty; c < Cc; c += 8) {
        float v = xb[c * Nc];
        s += v; s2 += v * v;
    }
    __shared__ float ss[8][33], sq[8][33];
    ss[ty][tx] = s; sq[ty][tx] = s2;
    __syncthreads();
    s = 0.f; s2 = 0.f;
#pragma unroll
    for (int j = 0; j < 8; j++) { s += ss[j][tx]; s2 += sq[j][tx]; }
    const float mean = s * (1.f / Cc);
    const float rstd = rsqrtf(s2 * (1.f / Cc) - mean * mean + 1e-5f);

    float* orow = g_xln + ((size_t)(b << 10) + n0 + tx) * Cc;
    for (int c = ty; c < Cc; c += 8) {
        float v = xb[c * Nc];
        orow[c] = (v - mean) * rstd * g[c] + be[c];
    }
}

// -------------------------------- dense bias precompute --------------------
__global__ void bias_pre_kernel(const int* __restrict__ rel_index,
                                const float* __restrict__ rpb)
{
    const int n = blockIdx.x;
    const int h = blockIdx.y;
    const int m = threadIdx.x << 2;
    const int4 ri = *(const int4*)(rel_index + n * Nc + m);
    float4 r;
    r.x = rpb[ri.x * NHc + h];
    r.y = rpb[ri.y * NHc + h];
    r.z = rpb[ri.z * NHc + h];
    r.w = rpb[ri.w * NHc + h];
    *(float4*)(g_bias + (((size_t)h << 10) + n) * Nc + m) = r;
}

// -------------------------------- QKV projection ---------------------------
__global__ __launch_bounds__(256) void qkv_gemm(
        const float* __restrict__ wq, const float* __restrict__ bq,
        const float* __restrict__ wkv, const float* __restrict__ bkv)
{
    const int n0 = blockIdx.x * 128;
    const int m0 = blockIdx.y * 128;
    const float* Wp = (n0 < MIDc) ? wq : (wkv - (size_t)MIDc * Cc);
    const float* bp = (n0 < MIDc) ? bq : (bkv - MIDc);

    float acc[2][4][2][4];
    gemm128<Cc>(g_xln, Wp, m0, n0, acc);

    const int tx = threadIdx.x & 15, ty = threadIdx.x >> 4;
#pragma unroll
    for (int a = 0; a < 2; a++)
#pragma unroll
    for (int i = 0; i < 4; i++) {
        const int m = micro_row(m0, ty, a, i);
        const int b = m >> 10, n = m & 1023;
#pragma unroll
        for (int bb = 0; bb < 2; bb++)
#pragma unroll
        for (int j = 0; j < 4; j++) {
            const int o = micro_col(n0, tx, bb, j);
            const float val = acc[a][i][bb][j] + bp[o];
            const int oo = (o >= 2 * MIDc) ? o - 2 * MIDc : (o >= MIDc ? o - MIDc : o);
            const int hh = oo / HDc, d = oo - hh * HDc;
            const size_t idx = ((size_t)(b * NHc + hh) * Nc + n) * HDc + d;
            if (o < MIDc)          g_Q[idx] = val;
            else if (o < 2 * MIDc) g_K[idx] = val;
            else                   g_V[idx] = val;
        }
    }
}

// -------------------------------- fused flash attention --------------------
// grid (8 q-tiles of 128 rows, 128 bh), 256 threads.
// Per thread: 8 S rows (split ty*4+i / +64) x 4 cols; O micro 8x3.
// No-max softmax (logits bounded); single row-sum reduction at the end.
__global__ __launch_bounds__(256, 2) void attn_kernel()
{
    const int q0 = blockIdx.x << 7;      // 128-query tile
    const int bh = blockIdx.y;
    const int h  = bh & 7;
    const float* Q  = g_Q + (size_t)bh * Nc * HDc;
    const float* K  = g_K + (size_t)bh * Nc * HDc;
    const float* V  = g_V + (size_t)bh * Nc * HDc;
    const float* Bp = g_bias + ((size_t)h << 20);

    __shared__ __align__(16) float sQ [48][132];  // [d][row], 128 rows
    __shared__ __align__(16) float sK [48][68];   // [d][col]
    __shared__ __align__(16) float sVT[48][68];   // [d][k]  (V transposed)
    __shared__ __align__(16) float sP [128][68];  // [row][k]

    const int tid = threadIdx.x;
    const int tx  = tid & 15, ty = tid >> 4;
    const int lrq = tid >> 1;            // 0..127 Q row handled by loader
    const int lq0 = (tid & 1) * 24;      // 0 or 24
    const int lr  = tid >> 2;            // 0..63 KV row handled by loader
    const int ld0 = (tid & 3) * 12;      // 0,12,24,36

    // ---- load Q tile (128 x 48), transposed into sQ[d][row] ----
    {
        const float4* qr = (const float4*)(Q + (size_t)(q0 + lrq) * HDc + lq0);
        float buf[24];
#pragma unroll
        for (int j = 0; j < 6; j++) *(float4*)&buf[j << 2] = qr[j];
#pragma unroll
        for (int j = 0; j < 24; j++) sQ[lq0 + j][lrq] = buf[j];
    }

    float lsum[2][4];
    float accO[2][4][3];
#pragma unroll
    for (int a = 0; a < 2; a++)
#pragma unroll
        for (int i = 0; i < 4; i++) {
            lsum[a][i] = 0.f;
            accO[a][i][0] = accO[a][i][1] = accO[a][i][2] = 0.f;
        }
    const float scale = 0.14433756729740644f;   // 48^-0.5

    for (int k0 = 0; k0 < Nc; k0 += 64) {
        // ---- load K and V tiles, both transposed [d][k] ----
        {
            const float4* kr = (const float4*)(K + (size_t)(k0 + lr) * HDc + ld0);
            const float4* vr = (const float4*)(V + (size_t)(k0 + lr) * HDc + ld0);
            float4 ka = kr[0], kb = kr[1], kc = kr[2];
            float4 va = vr[0], vb = vr[1], vc = vr[2];
            __syncthreads();   // previous iteration fully done with smem
            float kv[12] = {ka.x,ka.y,ka.z,ka.w, kb.x,kb.y,kb.z,kb.w, kc.x,kc.y,kc.z,kc.w};
            float vv[12] = {va.x,va.y,va.z,va.w, vb.x,vb.y,vb.z,vb.w, vc.x,vc.y,vc.z,vc.w};
#pragma unroll
            for (int j = 0; j < 12; j++) {
                sK [ld0 + j][lr] = kv[j];
                sVT[ld0 + j][lr] = vv[j];
            }
        }
        __syncthreads();       // tiles visible (also covers Q store on iter 0)

        // ---- prefetch bias (L2) so latency hides under the S GEMM ----
        float4 bi[2][4];
#pragma unroll
        for (int a = 0; a < 2; a++)
#pragma unroll
            for (int i = 0; i < 4; i++) {
                const int n = q0 + (a ? 64 : 0) + (ty << 2) + i;
                bi[a][i] = *(const float4*)(Bp + ((size_t)n << 10) + k0 + (tx << 2));
            }

        // ---- S = Q K^T (split 8x4 per thread) ----
        float s[2][4][4];
#pragma unroll
        for (int a = 0; a < 2; a++)
#pragma unroll
            for (int i = 0; i < 4; i++)
#pragma unroll
                for (int j = 0; j < 4; j++) s[a][i][j] = 0.f;
#pragma unroll
        for (int kk = 0; kk < 48; kk++) {
            const float4 qa = *(const float4*)&sQ[kk][ty << 2];
            const float4 qb = *(const float4*)&sQ[kk][64 + (ty << 2)];
            const float4 kv4 = *(const float4*)&sK[kk][tx << 2];
            const float qm[2][4] = {{qa.x, qa.y, qa.z, qa.w}, {qb.x, qb.y, qb.z, qb.w}};
            const float kn[4] = {kv4.x, kv4.y, kv4.z, kv4.w};
#pragma unroll
            for (int a = 0; a < 2; a++)
#pragma unroll
                for (int i = 0; i < 4; i++)
#pragma unroll
                    for (int j = 0; j < 4; j++)
                        s[a][i][j] = fmaf(qm[a][i], kn[j], s[a][i][j]);
        }

        // ---- exp(scale*s + bias), accumulate row-sum partials, store P ----
#pragma unroll
        for (int a = 0; a < 2; a++)
#pragma unroll
            for (int i = 0; i < 4; i++) {
                s[a][i][0] = __expf(fmaf(s[a][i][0], scale, bi[a][i].x));
                s[a][i][1] = __expf(fmaf(s[a][i][1], scale, bi[a][i].y));
                s[a][i][2] = __expf(fmaf(s[a][i][2], scale, bi[a][i].z));
                s[a][i][3] = __expf(fmaf(s[a][i][3], scale, bi[a][i].w));
                lsum[a][i] += (s[a][i][0] + s[a][i][1]) + (s[a][i][2] + s[a][i][3]);
                *(float4*)&sP[(a ? 64 : 0) + (ty << 2) + i][tx << 2] =
                    make_float4(s[a][i][0], s[a][i][1], s[a][i][2], s[a][i][3]);
            }
        __syncthreads();       // P visible

        // ---- O += P @ V  (both operands via LDS.128) ----
#pragma unroll
        for (int k4 = 0; k4 < 16; k4++) {
            float4 p4[2][4];
#pragma unroll
            for (int a = 0; a < 2; a++)
#pragma unroll
                for (int i = 0; i < 4; i++)
                    p4[a][i] = *(const float4*)&sP[(a ? 64 : 0) + (ty << 2) + i][k4 << 2];
            float4 vt[3];
#pragma unroll
            for (int j = 0; j < 3; j++)
                vt[j] = *(const float4*)&sVT[tx * 3 + j][k4 << 2];
#pragma unroll
            for (int a = 0; a < 2; a++)
#pragma unroll
                for (int i = 0; i < 4; i++) {
#pragma unroll
                    for (int j = 0; j < 3; j++) {
                        accO[a][i][j] = fmaf(p4[a][i].x, vt[j].x, accO[a][i][j]);
                        accO[a][i][j] = fmaf(p4[a][i].y, vt[j].y, accO[a][i][j]);
                        accO[a][i][j] = fmaf(p4[a][i].z, vt[j].z, accO[a][i][j]);
                        accO[a][i][j] = fmaf(p4[a][i].w, vt[j].w, accO[a][i][j]);
                    }
                }
        }
    }

    // ---- row-sum reduction across the 16 tx lanes, then write O ----
    const int b = bh >> 3;
#pragma unroll
    for (int a = 0; a < 2; a++)
#pragma unroll
        for (int i = 0; i < 4; i++) {
            float l = lsum[a][i];
#pragma unroll
            for (int o = 8; o > 0; o >>= 1) l += __shfl_xor_sync(~0u, l, o);
            const float inv = 1.f / l;
            const int n = q0 + (a ? 64 : 0) + (ty << 2) + i;
            float* orow = g_O + ((size_t)(b << 10) + n) * MIDc + h * HDc + tx * 3;
            orow[0] = accO[a][i][0] * inv;
            orow[1] = accO[a][i][1] * inv;
            orow[2] = accO[a][i][2] * inv;
        }
}

// -------------------------------- proj + residual --------------------------
__global__ __launch_bounds__(256) void proj_gemm(
        const float* __restrict__ wproj, const float* __restrict__ bproj,
        const float* __restrict__ x)
{
    const int n0 = blockIdx.x * 128;
    const int m0 = blockIdx.y * 128;
    float acc[2][4][2][4];
    gemm128<MIDc>(g_O, wproj, m0, n0, acc);

    const int tx = threadIdx.x & 15, ty = threadIdx.x >> 4;
#pragma unroll
    for (int a = 0; a < 2; a++)
#pragma unroll
    for (int i = 0; i < 4; i++) {
        const int m = micro_row(m0, ty, a, i);
        const int b = m >> 10, n = m & 1023;
#pragma unroll
        for (int bb = 0; bb < 2; bb++)
#pragma unroll
        for (int j = 0; j < 4; j++) {
            const int o = micro_col(n0, tx, bb, j);
            const float val = acc[a][i][bb][j] + bproj[o]
                            + x[(size_t)b * CN + (size_t)o * Nc + n];
            g_x2t[(size_t)m * Cc + o] = val;
        }
    }
}

// -------------------------------- LN2 (token-major rows) -------------------
__global__ void ln2_kernel(const float* __restrict__ g, const float* __restrict__ be)
{
    const int t    = blockIdx.x * 8 + (threadIdx.x >> 5);
    const int lane = threadIdx.x & 31;
    const float4* xr = (const float4*)(g_x2t + (size_t)t * Cc);

    float4 v[3];
    float s = 0.f, s2 = 0.f;
#pragma unroll
    for (int i = 0; i < 3; i++) {
        v[i] = xr[lane + 32 * i];
        s  += v[i].x + v[i].y + v[i].z + v[i].w;
        s2 += v[i].x * v[i].x + v[i].y * v[i].y + v[i].z * v[i].z + v[i].w * v[i].w;
    }
#pragma unroll
    for (int o = 16; o > 0; o >>= 1) {
        s  += __shfl_xor_sync(~0u, s, o);
        s2 += __shfl_xor_sync(~0u, s2, o);
    }
    const float mean = s * (1.f / Cc);
    const float rstd = rsqrtf(s2 * (1.f / Cc) - mean * mean + 1e-5f);

    const float4* g4 = (const float4*)g;
    const float4* b4 = (const float4*)be;
    float4* orow = (float4*)(g_h2t + (size_t)t * Cc);
#pragma unroll
    for (int i = 0; i < 3; i++) {
        const int c4 = lane + 32 * i;
        const float4 gg = g4[c4], bb = b4[c4], vv = v[i];
        float4 r;
        r.x = (vv.x - mean) * rstd * gg.x + bb.x;
        r.y = (vv.y - mean) * rstd * gg.y + bb.y;
        r.z = (vv.z - mean) * rstd * gg.z + bb.z;
        r.w = (vv.w - mean) * rstd * gg.w + bb.w;
        orow[c4] = r;
    }
}

// -------------------------------- MLP fc1 + exact GELU ---------------------
__global__ __launch_bounds__(256) void mlp1_gemm(
        const float* __restrict__ w1, const float* __restrict__ b1)
{
    const int n0 = blockIdx.x * 128;
    const int m0 = blockIdx.y * 128;
    float acc[2][4][2][4];
    gemm128<Cc>(g_h2t, w1, m0, n0, acc);

    const int tx = threadIdx.x & 15, ty = threadIdx.x >> 4;
#pragma unroll
    for (int a = 0; a < 2; a++)
#pragma unroll
    for (int i = 0; i < 4; i++) {
        const int m = micro_row(m0, ty, a, i);
#pragma unroll
        for (int bb = 0; bb < 2; bb++)
#pragma unroll
        for (int j = 0; j < 4; j++) {
            const int o = micro_col(n0, tx, bb, j);
            const float val = acc[a][i][bb][j] + b1[o];
            const float gl  = 0.5f * val * (1.f + erff(val * 0.70710678118654752f));
            g_m1[(size_t)m * HIDc + o] = gl;
        }
    }
}

// -------------------------------- MLP fc2 + final residual, NCHW out -------
__global__ __launch_bounds__(256) void mlp2_gemm(
        const float* __restrict__ w2, const float* __restrict__ b2,
        float* __restrict__ out)
{
    const int n0 = blockIdx.x * 128;
    const int m0 = blockIdx.y * 128;
    float acc[2][4][2][4];
    gemm128<HIDc>(g_m1, w2, m0, n0, acc);

    const int tx = threadIdx.x & 15, ty = threadIdx.x >> 4;
#pragma unroll
    for (int a = 0; a < 2; a++)
#pragma unroll
    for (int i = 0; i < 4; i++) {
        const int m = micro_row(m0, ty, a, i);
        const int b = m >> 10, n = m & 1023;
#pragma unroll
        for (int bb = 0; bb < 2; bb++)
#pragma unroll
        for (int j = 0; j < 4; j++) {
            const int o = micro_col(n0, tx, bb, j);
            const float val = acc[a][i][bb][j] + b2[o] + g_x2t[(size_t)m * Cc + o];
            out[(size_t)b * CN + (size_t)o * Nc + n] = val;
        }
    }
}

// ---------------------------------------------------------------------------
extern "C" void kernel_launch(void* const* d_in, const int* in_sizes, int n_in,
                              void* d_out, int out_size)
{
    const float* x     = (const float*)d_in[0];
    const float* rpb   = (const float*)d_in[1];
    const int*   ridx  = (const int*)  d_in[2];
    const float* ln1g  = (const float*)d_in[3];
    const float* ln1b  = (const float*)d_in[4];
    const float* ln2g  = (const float*)d_in[5];
    const float* ln2b  = (const float*)d_in[6];
    const float* wq    = (const float*)d_in[7];
    const float* bq    = (const float*)d_in[8];
    const float* wkv   = (const float*)d_in[9];
    const float* bkv   = (const float*)d_in[10];
    const float* wproj = (const float*)d_in[11];
    const float* bproj = (const float*)d_in[12];
    const float* w1    = (const float*)d_in[13];
    const float* b1    = (const float*)d_in[14];
    const float* w2    = (const float*)d_in[15];
    const float* b2    = (const float*)d_in[16];
    float* out = (float*)d_out;

    ln1_kernel     <<<Bc * (Nc / 32), dim3(32, 8)>>>(x, ln1g, ln1b);
    bias_pre_kernel<<<dim3(Nc, NHc), 256>>>(ridx, rpb);
    qkv_gemm       <<<dim3(9,  Mtok / 128), 256>>>(wq, bq, wkv, bkv);
    attn_kernel    <<<dim3(8, Bc * NHc), 256>>>();
    proj_gemm      <<<dim3(3,  Mtok / 128), 256>>>(wproj, bproj, x);
    ln2_kernel     <<<Mtok / 8, 256>>>(ln2g, ln2b);
    mlp1_gemm      <<<dim3(12, Mtok / 128), 256>>>(w1, b1);
    mlp2_gemm      <<<dim3(3,  Mtok / 128), 256>>>(w2, b2, out);
}